// round 8
// baseline (speedup 1.0000x reference)
#include <cuda_runtime.h>
#include <cuda_bf16.h>

// Shapes: query (N,T,C,L)=(32,64,256,64) fp32; key (T,N,C); out (T,N,C)
#define N_ 32
#define T_ 64
#define C_ 256
#define L_ 64
#define GRP 129                    // 64 scores + 1 softmax + 64 out per group
#define NGRP (N_ + 2)              // pipeline: out lags scores by 2 n-groups

__device__ float g_part[N_ * T_ * L_];   // per-(n,t) partial scores
__device__ float g_probs[N_ * L_];       // softmax probs per n
__device__ int   g_count[N_];            // scores arrivals   (self-cleaning)
__device__ int   g_flag[N_];             // softmax-ready flag
__device__ int   g_done[N_];             // out completions -> reset

// ---------------------------------------------------------------------------
// Single-launch pipelined kernel. Group g = bid/129:
//   role 0 (r<64):   scores for n=g      -- pure DRAM stream, NEVER waits
//   role 1 (r==64):  softmax for n=g-1   -- spins on count[n]==64 (short)
//   role 2 (r>64):   out for n=g-2       -- spins on flag[n]; q chunk is
//                                           ~8MB behind frontier => L2-hot
// All spin dependencies point to smaller bids -> scheduled earlier -> safe.
// ---------------------------------------------------------------------------
__global__ __launch_bounds__(256) void k_pipe(const float* __restrict__ q,
                                              const float* __restrict__ key,
                                              float* __restrict__ out) {
    const int g = blockIdx.x / GRP;
    const int r = blockIdx.x % GRP;
    const int tid = threadIdx.x;
    const int w = tid >> 5;
    const int lane = tid & 31;

    if (r < T_) {
        // ---------------- scores role (R6 float4 body) ----------------
        if (g >= N_) return;
        const int n = g, t = r;
        const size_t b = (size_t)n * T_ + t;
        const int half = lane >> 4;
        const int l4 = lane & 15;

        const float kreg = key[((size_t)t * N_ + n) * C_ + (w << 5) + lane];
        const float4* __restrict__ qb = reinterpret_cast<const float4*>(q);
        const size_t rowbase = b * C_;

        float4 acc = make_float4(0.f, 0.f, 0.f, 0.f);
        #pragma unroll
        for (int i = 0; i < 16; ++i) {
            const int rr = (i << 1) + half;
            const float kv = __shfl_sync(0xffffffffu, kreg, rr);
            const float4 qv = qb[(rowbase + (w << 5) + rr) * 16 + l4];
            acc.x = fmaf(kv, qv.x, acc.x);
            acc.y = fmaf(kv, qv.y, acc.y);
            acc.z = fmaf(kv, qv.z, acc.z);
            acc.w = fmaf(kv, qv.w, acc.w);
        }
        acc.x += __shfl_xor_sync(0xffffffffu, acc.x, 16);
        acc.y += __shfl_xor_sync(0xffffffffu, acc.y, 16);
        acc.z += __shfl_xor_sync(0xffffffffu, acc.z, 16);
        acc.w += __shfl_xor_sync(0xffffffffu, acc.w, 16);

        __shared__ float4 sm[8][16];
        if (half == 0) sm[w][l4] = acc;
        __syncthreads();
        if (tid < 16) {
            float4 tot = sm[0][tid];
            #pragma unroll
            for (int j = 1; j < 8; ++j) {
                const float4 v = sm[j][tid];
                tot.x += v.x; tot.y += v.y; tot.z += v.z; tot.w += v.w;
            }
            reinterpret_cast<float4*>(g_part + b * L_)[tid] = tot;
            __threadfence();
        }
        __syncthreads();
        if (tid == 0) atomicAdd(&g_count[n], 1);

    } else if (r == T_) {
        // ---------------- softmax role ----------------
        const int n = g - 1;
        if (n < 0 || n >= N_) return;

        if (tid == 0) {
            while (atomicAdd(&g_count[n], 0) != T_) __nanosleep(64);
            __threadfence();
        }
        __syncthreads();

        __shared__ float s_red[4];
        float s = 0.f, e = 0.f;
        if (tid < L_) {
            const float* __restrict__ p = g_part + (size_t)n * T_ * L_ + tid;
            #pragma unroll
            for (int t2 = 0; t2 < T_; ++t2) s += p[(size_t)t2 * L_];
            float m = s;
            #pragma unroll
            for (int off = 16; off; off >>= 1)
                m = fmaxf(m, __shfl_xor_sync(0xffffffffu, m, off));
            if (lane == 0) s_red[w] = m;
        }
        __syncthreads();
        if (tid < L_) {
            const float m = fmaxf(s_red[0], s_red[1]);
            e = __expf(s - m);
            float sum = e;
            #pragma unroll
            for (int off = 16; off; off >>= 1)
                sum += __shfl_xor_sync(0xffffffffu, sum, off);
            if (lane == 0) s_red[2 + w] = sum;
        }
        __syncthreads();
        if (tid < L_) {
            g_probs[n * L_ + tid] = e / (s_red[2] + s_red[3]);
            __threadfence();
        }
        __syncthreads();
        if (tid == 0) atomicExch(&g_flag[n], 1);

    } else {
        // ---------------- out role (L2-hot chunk, lag 2 groups) --------
        const int n = g - 2;
        if (n < 0) return;
        const int t = r - T_ - 1;
        const size_t b = (size_t)n * T_ + t;
        const int half = lane >> 4;
        const int l4 = lane & 15;

        if (tid == 0) {
            while (atomicAdd(&g_flag[n], 0) == 0) __nanosleep(64);
            __threadfence();
        }
        __syncthreads();

        const float4 pv = reinterpret_cast<const float4*>(g_probs + n * L_)[l4];
        const float4* __restrict__ qb = reinterpret_cast<const float4*>(q);
        const size_t rowbase = b * C_;
        float* __restrict__ ob = out + ((size_t)t * N_ + n) * C_;

        #pragma unroll 8
        for (int i = 0; i < 16; ++i) {
            const int c = (w << 5) + (i << 1) + half;
            const float4 qv = qb[(rowbase + c) * 16 + l4];
            float v = fmaf(qv.x, pv.x,
                      fmaf(qv.y, pv.y,
                      fmaf(qv.z, pv.z, qv.w * pv.w)));
            #pragma unroll
            for (int off = 8; off; off >>= 1)
                v += __shfl_xor_sync(0xffffffffu, v, off);
            if (l4 == 0) ob[c] = v;
        }

        // self-clean sync state for next graph replay
        __syncthreads();
        if (tid == 0) {
            const int old = atomicAdd(&g_done[n], 1);
            if (old == T_ - 1) {
                g_flag[n] = 0;
                g_count[n] = 0;
                g_done[n] = 0;
            }
        }
    }
}

extern "C" void kernel_launch(void* const* d_in, const int* in_sizes, int n_in,
                              void* d_out, int out_size) {
    const float* q   = (const float*)d_in[0];
    const float* key = (const float*)d_in[1];
    float* out = (float*)d_out;

    k_pipe<<<NGRP * GRP, 256>>>(q, key, out);
}